// round 2
// baseline (speedup 1.0000x reference)
#include <cuda_runtime.h>
#include <cstdint>

#define T_STEPS 1024
#define B_SZ    64
#define H_SZ    512
#define IN_SZ   512
#define G4      2048
#define NCTA    128
#define HS_STRIDE 516   // padded row stride for h in SMEM (16B-aligned, conflict-free)

// ---------------- scratch (static device allocations are allowed) ----------------
__device__ float    g_xp[(size_t)T_STEPS * B_SZ * G4];   // 512 MB: x @ Wx^T + b
__device__ unsigned g_bar_count;                          // zero-initialized
__device__ unsigned g_bar_gen;                            // monotonic across launches

// ---------------- helpers ----------------
__device__ __forceinline__ float sigf(float x) {
    return 1.0f / (1.0f + __expf(-x));
}
__device__ __forceinline__ float tanh_fast(float x) {
    float ax = fabsf(x);
    float e  = __expf(-2.0f * ax);
    float t  = (1.0f - e) / (1.0f + e);
    return copysignf(t, x);
}

__device__ __forceinline__ unsigned smem_u32(const void* p) {
    return (unsigned)__cvta_generic_to_shared(p);
}
__device__ __forceinline__ void cp_async16(unsigned dst, const void* src) {
    asm volatile("cp.async.ca.shared.global [%0], [%1], 16;" :: "r"(dst), "l"(src));
}
__device__ __forceinline__ void cp_async_wait_all() {
    asm volatile("cp.async.commit_group;\ncp.async.wait_group 0;" ::: "memory");
}

// Grid-wide barrier. Generation-counting: g_bar_gen is monotonic across launches
// (each launch reads its base first), g_bar_count self-resets each barrier.
// All 128 CTAs are co-resident (128 < 148 SMs, 1 CTA/SM) so this cannot deadlock.
__device__ __forceinline__ void grid_barrier(unsigned target) {
    __syncthreads();
    if (threadIdx.x == 0) {
        __threadfence();  // make this CTA's h writes visible before arriving
        unsigned prev = atomicAdd(&g_bar_count, 1);
        if (prev == NCTA - 1) {
            g_bar_count = 0;
            __threadfence();
            atomicExch(&g_bar_gen, target);
        } else {
            while (*((volatile unsigned*)&g_bar_gen) != target) { __nanosleep(40); }
            __threadfence();  // acquire: order subsequent h reads
        }
    }
    __syncthreads();
}

// =====================================================================
// Phase 1: xp[t,b,g] = sum_k x[t,b,k] * Wx[g,k] + (bx[g] + bh[g])
// M = T*B = 65536, N = 2048 (gate-major f,i,o,g), K = 512.  fp32 SIMT GEMM.
// =====================================================================
__global__ __launch_bounds__(256) void xp_gemm(
    const float* __restrict__ x,
    const float* __restrict__ Wx0, const float* __restrict__ Wx1,
    const float* __restrict__ Wx2, const float* __restrict__ Wx3,
    const float* __restrict__ bx0, const float* __restrict__ bx1,
    const float* __restrict__ bx2, const float* __restrict__ bx3,
    const float* __restrict__ bh0, const float* __restrict__ bh1,
    const float* __restrict__ bh2, const float* __restrict__ bh3)
{
    const int BM = 128, BN = 64, BK = 16;
    __shared__ float As[BK][BM];   // [k][m]
    __shared__ float Bs[BK][BN];   // [k][n]

    const int bx  = blockIdx.x;          // n-tile: 0..31
    const int by  = blockIdx.y;          // m-tile: 0..511
    const int tid = threadIdx.x;

    const int gate = bx >> 3;            // 512 cols per gate / 64 per tile
    const int gin0 = (bx & 7) * BN;      // col base within gate
    const float* W   = (gate == 0) ? Wx0 : (gate == 1) ? Wx1 : (gate == 2) ? Wx2 : Wx3;
    const float* bxp = (gate == 0) ? bx0 : (gate == 1) ? bx1 : (gate == 2) ? bx2 : bx3;
    const float* bhp = (gate == 0) ? bh0 : (gate == 1) ? bh1 : (gate == 2) ? bh2 : bh3;

    const int row0 = by * BM;
    const int tm   = tid & 15;           // m group (8 rows each)
    const int tn   = tid >> 4;           // n group (4 cols each), 0..15

    float acc[8][4];
    #pragma unroll
    for (int i = 0; i < 8; i++)
        #pragma unroll
        for (int j = 0; j < 4; j++) acc[i][j] = 0.0f;

    for (int kk = 0; kk < IN_SZ; kk += BK) {
        // A tile: 128 rows x 16 k = 512 float4 slots, 2 per thread
        #pragma unroll
        for (int it = 0; it < 2; it++) {
            int idx = tid + it * 256;
            int m = idx >> 2, k4 = idx & 3;
            float4 a = *(const float4*)&x[(size_t)(row0 + m) * IN_SZ + kk + k4 * 4];
            As[k4 * 4 + 0][m] = a.x; As[k4 * 4 + 1][m] = a.y;
            As[k4 * 4 + 2][m] = a.z; As[k4 * 4 + 3][m] = a.w;
        }
        // B tile: 64 rows x 16 k = 256 float4 slots, 1 per thread
        {
            int n = tid >> 2, k4 = tid & 3;
            float4 b = *(const float4*)&W[(size_t)(gin0 + n) * IN_SZ + kk + k4 * 4];
            Bs[k4 * 4 + 0][n] = b.x; Bs[k4 * 4 + 1][n] = b.y;
            Bs[k4 * 4 + 2][n] = b.z; Bs[k4 * 4 + 3][n] = b.w;
        }
        __syncthreads();

        #pragma unroll
        for (int k = 0; k < BK; k++) {
            float4 a0 = *(const float4*)&As[k][tm * 8];
            float4 a1 = *(const float4*)&As[k][tm * 8 + 4];
            float4 bv = *(const float4*)&Bs[k][tn * 4];
            float am[8] = {a0.x, a0.y, a0.z, a0.w, a1.x, a1.y, a1.z, a1.w};
            float bb[4] = {bv.x, bv.y, bv.z, bv.w};
            #pragma unroll
            for (int i = 0; i < 8; i++)
                #pragma unroll
                for (int j = 0; j < 4; j++)
                    acc[i][j] = fmaf(am[i], bb[j], acc[i][j]);
        }
        __syncthreads();
    }

    // epilogue: add (bx + bh), write xp
    float bias[4];
    #pragma unroll
    for (int j = 0; j < 4; j++) {
        int g = gin0 + tn * 4 + j;
        bias[j] = bxp[g] + bhp[g];
    }
    #pragma unroll
    for (int i = 0; i < 8; i++) {
        size_t m = (size_t)(row0 + tm * 8 + i);
        float4 o;
        o.x = acc[i][0] + bias[0];
        o.y = acc[i][1] + bias[1];
        o.z = acc[i][2] + bias[2];
        o.w = acc[i][3] + bias[3];
        *(float4*)&g_xp[m * G4 + (size_t)gate * 512 + gin0 + tn * 4] = o;
    }
}

// =====================================================================
// Phase 2: persistent recurrence. 128 CTAs x 256 threads.
// CTA ct owns hidden units j in [4ct, 4ct+4): 16 Wh rows (4 gates x 4 units),
// kept transposed in SMEM. c-slice lives in SMEM for the whole kernel.
// h buffer == h_seq output rows; grid barrier per step.
// out layout: h_seq (T,B,H) | h_final (B,H) | c_final (B,H)
// =====================================================================
__global__ __launch_bounds__(256) void lstm_rec(
    const float* __restrict__ Whf, const float* __restrict__ Whi,
    const float* __restrict__ Who, const float* __restrict__ Whg,
    float* __restrict__ out)
{
    extern __shared__ float sm[];
    float* ws = sm;                           // [512][16]  transposed Wh slice (32 KB)
    float* hs = ws + 512 * 16;                // [64][516]  h_{t-1}, padded (129 KB)
    float* zb = hs + 64 * HS_STRIDE;          // [16][65]   z scratch
    float* cb = zb + 16 * 65;                 // [256]      c state (4 units x 64 batch)
    __shared__ unsigned s_base;

    const int ct  = blockIdx.x;
    const int tid = threadIdx.x;
    const int j0  = ct * 4;

    // Load this CTA's 16 Wh rows, transposed to ws[k][r], r = q*4 + jl
    for (int idx = tid; idx < 16 * 512; idx += 256) {
        int r = idx >> 9;
        int k = idx & 511;
        int q = r >> 2, jl = r & 3;
        const float* whp = (q == 0) ? Whf : (q == 1) ? Whi : (q == 2) ? Who : Whg;
        ws[k * 16 + r] = whp[(size_t)(j0 + jl) * H_SZ + k];
    }
    cb[tid] = 0.0f;
    if (tid == 0) s_base = *((volatile unsigned*)&g_bar_gen);
    __syncthreads();
    const unsigned base = s_base;

    // compute-phase mapping: thread -> rows (2ro, 2ro+1), batches (bg, bg+32)
    const int ro  = tid & 7;
    const int bg  = tid >> 3;                 // 0..31
    const int b0  = bg, b1 = bg + 32;
    const int q   = ro >> 1;
    const int jl2 = (2 * ro) & 3;
    const int g0  = q * 512 + j0 + jl2;       // global gate-row of acc row r0 (r1 = g0+1)

    // update-phase mapping: thread -> (hidden unit ujl, batch ub)
    const int ujl = tid >> 6;
    const int ub  = tid & 63;

    const float* hrow0 = hs + b0 * HS_STRIDE;
    const float* hrow1 = hs + b1 * HS_STRIDE;
    const float* wp    = ws + 2 * ro;

    for (int t = 0; t < T_STEPS; t++) {
        // prefetch xp early (independent of h)
        float2 xv0 = *(const float2*)&g_xp[((size_t)t * B_SZ + b0) * G4 + g0];
        float2 xv1 = *(const float2*)&g_xp[((size_t)t * B_SZ + b1) * G4 + g0];

        float a00 = 0.f, a01 = 0.f, a10 = 0.f, a11 = 0.f;
        if (t > 0) {
            // stage h_{t-1} (= out row t-1) into SMEM via cp.async
            const float* hsrc = out + (size_t)(t - 1) * B_SZ * H_SZ;
            #pragma unroll
            for (int i = 0; i < 32; i++) {
                int idx = tid + i * 256;       // 8192 float4 total
                int b = idx >> 7, k4 = idx & 127;
                cp_async16(smem_u32(hs + b * HS_STRIDE + k4 * 4),
                           hsrc + (size_t)b * H_SZ + k4 * 4);
            }
            cp_async_wait_all();
            __syncthreads();

            #pragma unroll 8
            for (int k = 0; k < 512; k++) {
                float2 w = *(const float2*)&wp[k * 16];
                float h0v = hrow0[k];
                float h1v = hrow1[k];
                a00 = fmaf(w.x, h0v, a00);
                a01 = fmaf(w.x, h1v, a01);
                a10 = fmaf(w.y, h0v, a10);
                a11 = fmaf(w.y, h1v, a11);
            }
        }

        zb[(2 * ro) * 65 + b0]     = a00 + xv0.x;
        zb[(2 * ro + 1) * 65 + b0] = a10 + xv0.y;
        zb[(2 * ro) * 65 + b1]     = a01 + xv1.x;
        zb[(2 * ro + 1) * 65 + b1] = a11 + xv1.y;
        __syncthreads();

        // pointwise gate update: rows f=jl, i=4+jl, o=8+jl, g=12+jl
        {
            float zf = zb[(0  + ujl) * 65 + ub];
            float zi = zb[(4  + ujl) * 65 + ub];
            float zo = zb[(8  + ujl) * 65 + ub];
            float zg = zb[(12 + ujl) * 65 + ub];
            float f  = sigf(zf);
            float ii = sigf(zi);
            float o  = sigf(zo);
            float g  = tanh_fast(zg);
            float c  = fmaf(f, cb[tid], ii * g);
            float h  = o * tanh_fast(c);
            cb[tid] = c;
            out[((size_t)t * B_SZ + ub) * H_SZ + j0 + ujl] = h;
            if (t == T_STEPS - 1) {
                size_t tail = (size_t)T_STEPS * B_SZ * H_SZ;
                out[tail + (size_t)ub * H_SZ + j0 + ujl] = h;                    // h_final
                out[tail + (size_t)B_SZ * H_SZ + (size_t)ub * H_SZ + j0 + ujl] = c; // c_final
            }
        }

        grid_barrier(base + (unsigned)t + 1u);
    }
}

// =====================================================================
extern "C" void kernel_launch(void* const* d_in, const int* in_sizes, int n_in,
                              void* d_out, int out_size)
{
    const float* x   = (const float*)d_in[0];
    const float* Wxf = (const float*)d_in[1];  const float* bxf = (const float*)d_in[2];
    const float* Whf = (const float*)d_in[3];  const float* bhf = (const float*)d_in[4];
    const float* Wxi = (const float*)d_in[5];  const float* bxi = (const float*)d_in[6];
    const float* Whi = (const float*)d_in[7];  const float* bhi = (const float*)d_in[8];
    const float* Wxo = (const float*)d_in[9];  const float* bxo = (const float*)d_in[10];
    const float* Who = (const float*)d_in[11]; const float* bho = (const float*)d_in[12];
    const float* Wxg = (const float*)d_in[13]; const float* bxg = (const float*)d_in[14];
    const float* Whg = (const float*)d_in[15]; const float* bhg = (const float*)d_in[16];
    float* out = (float*)d_out;

    // Phase 1: input projections for all timesteps
    dim3 ggrid(G4 / 64, (T_STEPS * B_SZ) / 128);
    xp_gemm<<<ggrid, 256>>>(x, Wxf, Wxi, Wxo, Wxg,
                            bxf, bxi, bxo, bxg,
                            bhf, bhi, bho, bhg);

    // Phase 2: persistent recurrence
    const int smem_bytes = (512 * 16 + 64 * HS_STRIDE + 16 * 65 + 256) * 4;
    cudaFuncSetAttribute(lstm_rec, cudaFuncAttributeMaxDynamicSharedMemorySize, smem_bytes);
    lstm_rec<<<NCTA, 256, smem_bytes>>>(Whf, Whi, Who, Whg, out);
}